// round 4
// baseline (speedup 1.0000x reference)
#include <cuda_runtime.h>

#define NN 1024
#define HH 512
#define TI 16            // output rows per CTA chunk
#define WCOLS 64         // output cols per warp
#define NWARPS 8
#define NTHREADS (NWARPS*32)

__device__ __forceinline__ int reflC(int c) {
    if (c < 0) c = -c;
    if (c > HH - 1) c = 2 * (HH - 1) - c;
    return c;
}

struct V4 { float s0, s1, d0, d1; };

// Row lift of raw row pointer rp for this lane's 2 output columns.
// haloA/haloB are precomputed reflected halo float-offsets (valid on lanes 0,31).
__device__ __forceinline__ V4 rowlift(const float* __restrict__ rp,
                                      int lane, bool edge,
                                      int haloA, int haloB, int loff) {
    float4 v = *reinterpret_cast<const float4*>(rp + loff);
    float evenA = 0.f, oddA = 0.f, evenB = 0.f;
    if (edge) {                                   // predicated, lanes 0 & 31 only
        float2 ha = *reinterpret_cast<const float2*>(rp + haloA);
        evenA = ha.x; oddA = ha.y;
        evenB = rp[haloB];
    }
    // even-neighbor exchange
    float eL = __shfl_up_sync(0xffffffffu, v.z, 1);   // even[2j-1]
    if (lane == 0)  eL = evenA;
    float eR = __shfl_down_sync(0xffffffffu, v.x, 1); // even[2j+2]
    if (lane == 31) eR = evenA;
    float d0 = v.y - 0.5f * (eL + v.z);   // d[2j]   = odd - 1/2(even[c-1]+even[c+1])
    float d1 = v.w - 0.5f * (v.x + eR);   // d[2j+1]
    // d-neighbor exchange
    float dL = __shfl_up_sync(0xffffffffu, d1, 1);    // d[2j-1]
    if (lane == 0)  dL = oddA - 0.5f * (evenB + v.x); // d[C0-1] via reflected halo
    float dR = __shfl_down_sync(0xffffffffu, d0, 1);  // d[2j+2]
    if (lane == 31) dR = oddA - 0.5f * (v.z + evenB); // d[C0+64] via reflected halo
    V4 r;
    r.d0 = d0; r.d1 = d1;
    r.s0 = v.x + 0.25f * (dL + d1);
    r.s1 = v.z + 0.25f * (d0 + dR);
    return r;
}

#define LIFT(i_half_even_or_odd_row) \
    rowlift(xp + (size_t)(i_half_even_or_odd_row) * NN, lane, edge, haloA, haloB, loff)

__global__ __launch_bounds__(NTHREADS, 5)
void ilwt2d_warp_kernel(const float* __restrict__ x, float* __restrict__ out) {
    const int lane = threadIdx.x & 31;
    const int w = threadIdx.x >> 5;
    const int C0 = w * WCOLS;
    const int i0 = blockIdx.x * TI;
    const int img = blockIdx.y;
    const float* __restrict__ xp = x + (size_t)img * NN * NN;

    const int b = img / 3, ch = img - 3 * b;
    const size_t plane = (size_t)HH * HH;
    float* __restrict__ outb = out + (size_t)b * 12 * plane + (size_t)ch * plane;
    const int ocol = C0 + 2 * lane;

    // Precompute halo addressing (column reflection baked into addresses).
    const bool edge = (lane == 0) || (lane == 31);
    int haloA, haloB;
    if (lane == 31) {
        haloA = 2 * reflC(C0 + 64);      // {even,odd}[C0+64]
        haloB = 2 * reflC(C0 + 65);      // even[C0+65]
    } else {
        haloA = 2 * reflC(C0 - 1);       // {even,odd}[C0-1]
        haloB = 2 * reflC(C0 - 2);       // even[C0-2]
    }
    const int loff = 2 * C0 + 4 * lane;

    // -------- prologue: build column-lift pipeline state --------
    // E[i] = rowlift(raw row 2*refl(i)), O[i] = rowlift(raw row 2*refl(i)+1)
    V4 Ecur  = LIFT(2 * i0);                         // E[i0]
    V4 Em    = LIFT(2 * reflC(i0 - 1));              // E[i0-1]
    V4 Em2   = LIFT(2 * reflC(i0 - 2));              // E[i0-2]
    V4 Om1   = LIFT(2 * reflC(i0 - 1) + 1);          // O[i0-1]
    V4 Dprev;                                        // Dcol[i0-1]
    Dprev.s0 = Om1.s0 - 0.5f * (Em2.s0 + Ecur.s0);
    Dprev.s1 = Om1.s1 - 0.5f * (Em2.s1 + Ecur.s1);
    Dprev.d0 = Om1.d0 - 0.5f * (Em2.d0 + Ecur.d0);
    Dprev.d1 = Om1.d1 - 0.5f * (Em2.d1 + Ecur.d1);
    V4 Enext = LIFT(2 * reflC(i0 + 1));              // E[i0+1]
    V4 O0    = LIFT(2 * i0 + 1);                     // O[i0]
    V4 Dcur;                                         // Dcol[i0]
    Dcur.s0 = O0.s0 - 0.5f * (Em.s0 + Enext.s0);
    Dcur.s1 = O0.s1 - 0.5f * (Em.s1 + Enext.s1);
    Dcur.d0 = O0.d0 - 0.5f * (Em.d0 + Enext.d0);
    Dcur.d1 = O0.d1 - 0.5f * (Em.d1 + Enext.d1);

    // -------- main streaming loop over output rows --------
    #pragma unroll 2
    for (int t = 0; t < TI; ++t) {
        const int i = i0 + t;
        V4 En2 = LIFT(2 * reflC(i + 2));             // E[i+2]
        V4 Oi1 = LIFT(2 * reflC(i + 1) + 1);         // O[i+1]
        V4 Dnext;                                    // Dcol[i+1]
        Dnext.s0 = Oi1.s0 - 0.5f * (Ecur.s0 + En2.s0);
        Dnext.s1 = Oi1.s1 - 0.5f * (Ecur.s1 + En2.s1);
        Dnext.d0 = Oi1.d0 - 0.5f * (Ecur.d0 + En2.d0);
        Dnext.d1 = Oi1.d1 - 0.5f * (Ecur.d1 + En2.d1);

        float2 ll = { Ecur.s0 + 0.25f * (Dprev.s0 + Dnext.s0),
                      Ecur.s1 + 0.25f * (Dprev.s1 + Dnext.s1) };
        float2 lh = { Dcur.s0, Dcur.s1 };
        float2 hl = { Ecur.d0 + 0.25f * (Dprev.d0 + Dnext.d0),
                      Ecur.d1 + 0.25f * (Dprev.d1 + Dnext.d1) };
        float2 hh = { Dcur.d0, Dcur.d1 };

        const size_t o = (size_t)i * HH + ocol;
        *reinterpret_cast<float2*>(outb + o)             = ll;
        *reinterpret_cast<float2*>(outb + 3 * plane + o) = lh;
        *reinterpret_cast<float2*>(outb + 6 * plane + o) = hl;
        *reinterpret_cast<float2*>(outb + 9 * plane + o) = hh;

        Ecur = Enext; Enext = En2;
        Dprev = Dcur; Dcur = Dnext;
    }
}

extern "C" void kernel_launch(void* const* d_in, const int* in_sizes, int n_in,
                              void* d_out, int out_size) {
    const float* x = (const float*)d_in[0];
    float* out = (float*)d_out;
    dim3 grid(HH / TI, 24);   // 32 x 24 = 768 CTAs, 8 warps each
    ilwt2d_warp_kernel<<<grid, NTHREADS>>>(x, out);
}

// round 6
// speedup vs baseline: 1.1430x; 1.1430x over previous
#include <cuda_runtime.h>

#define NN 1024
#define HH 512
#define TI 32            // output rows per CTA chunk
#define WCOLS 64         // output cols per warp
#define NWARPS 8
#define NTHREADS (NWARPS*32)

__device__ __forceinline__ int reflC(int c) {
    if (c < 0) c = -c;
    if (c > HH - 1) c = 2 * (HH - 1) - c;
    return c;
}

struct V4 { float s0, s1, d0, d1; };

// Shuffle-free row lift: lane owns output cols {2j, 2j+1} (raw floats 4j..4j+3).
// Three overlapping float4 loads supply the full 12-float window; neighbor data
// comes from L1 (same cache lines as adjacent lanes' loads), not SHFL.
__device__ __forceinline__ V4 rowlift(const float* __restrict__ rp,
                                      int loff, int offA, int offC,
                                      bool lEdge, bool rEdge) {
    const float4 B = *reinterpret_cast<const float4*>(rp + loff);   // raw[4j..4j+3]
    const float4 A = *reinterpret_cast<const float4*>(rp + offA);   // raw[4j-4..4j-1]
    const float4 C = *reinterpret_cast<const float4*>(rp + offC);   // raw[4j+4..4j+7]
    float dm1 = A.w - 0.5f * (A.x + B.x);   // d[2j-1]
    float d0  = B.y - 0.5f * (A.z + B.z);   // d[2j]
    float d1  = B.w - 0.5f * (B.x + C.x);   // d[2j+1]
    float d2  = C.y - 0.5f * (B.z + C.z);   // d[2j+2]
    if (lEdge) { dm1 = d1; d0 = B.y - B.z; }          // d[-1]=d[1]; even[-1]=even[1]
    if (rEdge) { d1 = B.w - B.x; d2 = d0; }           // even[512]=even[510]; d[512]=d[510]
    V4 r;
    r.s0 = B.x + 0.25f * (dm1 + d1);
    r.s1 = B.z + 0.25f * (d0 + d2);
    r.d0 = d0; r.d1 = d1;
    return r;
}

#define LIFT(rawrow) \
    rowlift(xp + (size_t)(rawrow) * NN, loff, offA, offC, lEdge, rEdge)

__global__ __launch_bounds__(NTHREADS, 3)
void ilwt2d_warp_kernel(const float* __restrict__ x, float* __restrict__ out) {
    const int lane = threadIdx.x & 31;
    const int w = threadIdx.x >> 5;
    const int C0 = w * WCOLS;
    const int i0 = blockIdx.x * TI;
    const int img = blockIdx.y;
    const float* __restrict__ xp = x + (size_t)img * NN * NN;

    const int b = img / 3, ch = img - 3 * b;
    const size_t plane = (size_t)HH * HH;
    float* __restrict__ outb = out + (size_t)b * 12 * plane + (size_t)ch * plane;
    const int ocol = C0 + 2 * lane;

    const int loff = 2 * C0 + 4 * lane;               // raw float offset 4j
    const bool lEdge = (loff == 0);
    const bool rEdge = (loff == NN - 4);              // last 4 floats of the 1024-wide raw row
    const int offA = lEdge ? loff : loff - 4;
    const int offC = rEdge ? loff : loff + 4;

    // -------- prologue: build column-lift pipeline state --------
    V4 Ecur  = LIFT(2 * i0);                          // E[i0]
    V4 Em    = LIFT(2 * reflC(i0 - 1));               // E[i0-1]
    V4 Em2   = LIFT(2 * reflC(i0 - 2));               // E[i0-2]
    V4 Om1   = LIFT(2 * reflC(i0 - 1) + 1);           // O[i0-1]
    V4 Dprev;                                         // Dcol[i0-1]
    Dprev.s0 = Om1.s0 - 0.5f * (Em2.s0 + Ecur.s0);
    Dprev.s1 = Om1.s1 - 0.5f * (Em2.s1 + Ecur.s1);
    Dprev.d0 = Om1.d0 - 0.5f * (Em2.d0 + Ecur.d0);
    Dprev.d1 = Om1.d1 - 0.5f * (Em2.d1 + Ecur.d1);
    V4 Enext = LIFT(2 * reflC(i0 + 1));               // E[i0+1]
    V4 O0    = LIFT(2 * i0 + 1);                      // O[i0]
    V4 Dcur;                                          // Dcol[i0]
    Dcur.s0 = O0.s0 - 0.5f * (Em.s0 + Enext.s0);
    Dcur.s1 = O0.s1 - 0.5f * (Em.s1 + Enext.s1);
    Dcur.d0 = O0.d0 - 0.5f * (Em.d0 + Enext.d0);
    Dcur.d1 = O0.d1 - 0.5f * (Em.d1 + Enext.d1);

    // -------- main streaming loop over output rows --------
    #pragma unroll 4
    for (int t = 0; t < TI; ++t) {
        const int i = i0 + t;
        V4 En2 = LIFT(2 * reflC(i + 2));              // E[i+2]
        V4 Oi1 = LIFT(2 * reflC(i + 1) + 1);          // O[i+1]
        V4 Dnext;                                     // Dcol[i+1]
        Dnext.s0 = Oi1.s0 - 0.5f * (Ecur.s0 + En2.s0);
        Dnext.s1 = Oi1.s1 - 0.5f * (Ecur.s1 + En2.s1);
        Dnext.d0 = Oi1.d0 - 0.5f * (Ecur.d0 + En2.d0);
        Dnext.d1 = Oi1.d1 - 0.5f * (Ecur.d1 + En2.d1);

        float2 ll = { Ecur.s0 + 0.25f * (Dprev.s0 + Dnext.s0),
                      Ecur.s1 + 0.25f * (Dprev.s1 + Dnext.s1) };
        float2 lh = { Dcur.s0, Dcur.s1 };
        float2 hl = { Ecur.d0 + 0.25f * (Dprev.d0 + Dnext.d0),
                      Ecur.d1 + 0.25f * (Dprev.d1 + Dnext.d1) };
        float2 hh = { Dcur.d0, Dcur.d1 };

        const size_t o = (size_t)i * HH + ocol;
        *reinterpret_cast<float2*>(outb + o)             = ll;
        *reinterpret_cast<float2*>(outb + 3 * plane + o) = lh;
        *reinterpret_cast<float2*>(outb + 6 * plane + o) = hl;
        *reinterpret_cast<float2*>(outb + 9 * plane + o) = hh;

        Ecur = Enext; Enext = En2;
        Dprev = Dcur; Dcur = Dnext;
    }
}

extern "C" void kernel_launch(void* const* d_in, const int* in_sizes, int n_in,
                              void* d_out, int out_size) {
    const float* x = (const float*)d_in[0];
    float* out = (float*)d_out;
    dim3 grid(HH / TI, 24);   // 16 x 24 = 384 CTAs, 8 warps each
    ilwt2d_warp_kernel<<<grid, NTHREADS>>>(x, out);
}

// round 7
// speedup vs baseline: 1.2267x; 1.0733x over previous
#include <cuda_runtime.h>

#define NN 1024
#define HH 512
#define TI 32            // output rows per CTA chunk
#define WCOLS 64         // output cols per warp
#define NWARPS 8
#define NTHREADS (NWARPS*32)
#define PF 6             // prefetch distance in output rows

__device__ __forceinline__ int reflC(int c) {
    if (c < 0) c = -c;
    if (c > HH - 1) c = 2 * (HH - 1) - c;
    return c;
}

__device__ __forceinline__ void pfL2(const float* p) {
    asm volatile("prefetch.global.L2 [%0];" :: "l"(p));
}

__device__ __forceinline__ void stcs2(float* p, float a, float b) {
    asm volatile("st.global.cs.v2.f32 [%0], {%1,%2};" :: "l"(p), "f"(a), "f"(b) : "memory");
}

struct V4 { float s0, s1, d0, d1; };

// Shuffle-free row lift: lane owns output cols {2j, 2j+1} (raw floats 4j..4j+3).
// Three overlapping float4 loads supply the full 12-float window; neighbor data
// comes from L1 (same cache lines as adjacent lanes' loads), not SHFL.
__device__ __forceinline__ V4 rowlift(const float* __restrict__ rp,
                                      int loff, int offA, int offC,
                                      bool lEdge, bool rEdge) {
    const float4 B = *reinterpret_cast<const float4*>(rp + loff);   // raw[4j..4j+3]
    const float4 A = *reinterpret_cast<const float4*>(rp + offA);   // raw[4j-4..4j-1]
    const float4 C = *reinterpret_cast<const float4*>(rp + offC);   // raw[4j+4..4j+7]
    float dm1 = A.w - 0.5f * (A.x + B.x);   // d[2j-1]
    float d0  = B.y - 0.5f * (A.z + B.z);   // d[2j]
    float d1  = B.w - 0.5f * (B.x + C.x);   // d[2j+1]
    float d2  = C.y - 0.5f * (B.z + C.z);   // d[2j+2]
    if (lEdge) { dm1 = d1; d0 = B.y - B.z; }          // d[-1]=d[1]; even[-1]=even[1]
    if (rEdge) { d1 = B.w - B.x; d2 = d0; }           // even[512]=even[510]; d[512]=d[510]
    V4 r;
    r.s0 = B.x + 0.25f * (dm1 + d1);
    r.s1 = B.z + 0.25f * (d0 + d2);
    r.d0 = d0; r.d1 = d1;
    return r;
}

#define LIFT(rawrow) \
    rowlift(xp + (size_t)(rawrow) * NN, loff, offA, offC, lEdge, rEdge)

__global__ __launch_bounds__(NTHREADS, 3)
void ilwt2d_warp_kernel(const float* __restrict__ x, float* __restrict__ out) {
    const int lane = threadIdx.x & 31;
    const int w = threadIdx.x >> 5;
    const int C0 = w * WCOLS;
    const int i0 = blockIdx.x * TI;
    const int img = blockIdx.y;
    const float* __restrict__ xp = x + (size_t)img * NN * NN;

    const int b = img / 3, ch = img - 3 * b;
    const size_t plane = (size_t)HH * HH;
    float* __restrict__ outb = out + (size_t)b * 12 * plane + (size_t)ch * plane;
    const int ocol = C0 + 2 * lane;

    const int loff = 2 * C0 + 4 * lane;               // raw float offset 4j
    const bool lEdge = (loff == 0);
    const bool rEdge = (loff == NN - 4);              // last 4 floats of the raw row
    const int offA = lEdge ? loff : loff - 4;
    const int offC = rEdge ? loff : loff + 4;

    // -------- prologue prefetch burst: rows consumed in the first PF iterations --------
    {
        int rlo = 2 * i0 + 4;
        #pragma unroll
        for (int r = 0; r < 2 * PF; ++r) {
            int rr = rlo + r; if (rr > NN - 1) rr = NN - 1;
            pfL2(xp + (size_t)rr * NN + loff);
        }
    }

    // -------- prologue: build column-lift pipeline state --------
    V4 Ecur  = LIFT(2 * i0);                          // E[i0]
    V4 Em    = LIFT(2 * reflC(i0 - 1));               // E[i0-1]
    V4 Em2   = LIFT(2 * reflC(i0 - 2));               // E[i0-2]
    V4 Om1   = LIFT(2 * reflC(i0 - 1) + 1);           // O[i0-1]
    V4 Dprev;                                         // Dcol[i0-1]
    Dprev.s0 = Om1.s0 - 0.5f * (Em2.s0 + Ecur.s0);
    Dprev.s1 = Om1.s1 - 0.5f * (Em2.s1 + Ecur.s1);
    Dprev.d0 = Om1.d0 - 0.5f * (Em2.d0 + Ecur.d0);
    Dprev.d1 = Om1.d1 - 0.5f * (Em2.d1 + Ecur.d1);
    V4 Enext = LIFT(2 * reflC(i0 + 1));               // E[i0+1]
    V4 O0    = LIFT(2 * i0 + 1);                      // O[i0]
    V4 Dcur;                                          // Dcol[i0]
    Dcur.s0 = O0.s0 - 0.5f * (Em.s0 + Enext.s0);
    Dcur.s1 = O0.s1 - 0.5f * (Em.s1 + Enext.s1);
    Dcur.d0 = O0.d0 - 0.5f * (Em.d0 + Enext.d0);
    Dcur.d1 = O0.d1 - 0.5f * (Em.d1 + Enext.d1);

    // -------- main streaming loop over output rows --------
    #pragma unroll 4
    for (int t = 0; t < TI; ++t) {
        const int i = i0 + t;

        // prefetch the two raw rows consumed PF iterations from now
        {
            int ra = 2 * (i + PF) + 3; if (ra > NN - 1) ra = NN - 1;
            int rb = ra + 1;           if (rb > NN - 1) rb = NN - 1;
            pfL2(xp + (size_t)ra * NN + loff);
            pfL2(xp + (size_t)rb * NN + loff);
        }

        V4 En2 = LIFT(2 * reflC(i + 2));              // E[i+2]
        V4 Oi1 = LIFT(2 * reflC(i + 1) + 1);          // O[i+1]
        V4 Dnext;                                     // Dcol[i+1]
        Dnext.s0 = Oi1.s0 - 0.5f * (Ecur.s0 + En2.s0);
        Dnext.s1 = Oi1.s1 - 0.5f * (Ecur.s1 + En2.s1);
        Dnext.d0 = Oi1.d0 - 0.5f * (Ecur.d0 + En2.d0);
        Dnext.d1 = Oi1.d1 - 0.5f * (Ecur.d1 + En2.d1);

        float2 ll = { Ecur.s0 + 0.25f * (Dprev.s0 + Dnext.s0),
                      Ecur.s1 + 0.25f * (Dprev.s1 + Dnext.s1) };
        float2 hl = { Ecur.d0 + 0.25f * (Dprev.d0 + Dnext.d0),
                      Ecur.d1 + 0.25f * (Dprev.d1 + Dnext.d1) };

        float* op = outb + (size_t)i * HH + ocol;
        stcs2(op,             ll.x, ll.y);
        stcs2(op + 3 * plane, Dcur.s0, Dcur.s1);
        stcs2(op + 6 * plane, hl.x, hl.y);
        stcs2(op + 9 * plane, Dcur.d0, Dcur.d1);

        Ecur = Enext; Enext = En2;
        Dprev = Dcur; Dcur = Dnext;
    }
}

extern "C" void kernel_launch(void* const* d_in, const int* in_sizes, int n_in,
                              void* d_out, int out_size) {
    const float* x = (const float*)d_in[0];
    float* out = (float*)d_out;
    dim3 grid(HH / TI, 24);   // 16 x 24 = 384 CTAs, 8 warps each
    ilwt2d_warp_kernel<<<grid, NTHREADS>>>(x, out);
}